// round 9
// baseline (speedup 1.0000x reference)
#include <cuda_runtime.h>
#include <cstdint>

#define NS 128
#define NA 32
#define NB 64
#define NT 4096

#define CL     1024            // logged span per chunk (multiple of 8)
#define NC     4               // chunks per batch
#define WARM   32              // warmup steps for chunks > 0 (0.25^31 ~ 2e-19)
#define TOKMAX (CL + WARM)

typedef unsigned long long ull;

__device__ __forceinline__ void ffma2(ull& d, ull a, ull b) {
    asm("fma.rn.f32x2 %0, %1, %2, %3;" : "=l"(d) : "l"(a), "l"(b), "l"(d));
}
__device__ __forceinline__ ull add2(ull a, ull b) {
    ull d; asm("add.rn.f32x2 %0, %1, %2;" : "=l"(d) : "l"(a), "l"(b)); return d;
}
__device__ __forceinline__ void unpack2(float& lo, float& hi, ull v) {
    asm("mov.b64 {%0, %1}, %2;" : "=f"(lo), "=f"(hi) : "l"(v));
}
__device__ __forceinline__ ull pack2(float lo, float hi) {
    ull d; asm("mov.b64 %0, {%1, %2};" : "=l"(d) : "f"(lo), "f"(hi)); return d;
}

__global__ void zero_out(float* out) { out[threadIdx.x] = 0.0f; }

// grid = 256: CTA handles (batch b = blockIdx>>2, chunk c = blockIdx&3).
// 512 threads, tid = 4j + h: state j, quarter h covers rows [32h, 32h+32).
// 4-way dot split -> aR is only 16 ull (32 regs) so TWO 512-thread CTAs
// co-reside per SM at <=64 regs/thread: 8 warps/SMSP of independent streams
// hide the serial chain (LDS 29 + ffma chain + shfl + barrier).
// Quarter combine: shfl_xor 1,2 within the quad.
// Alpha buffer: quarter q at float-offset 36q (chunk stride 144B) -> each
// warp LDS.128 touches 4 disjoint-bank 16B lines = 1 wavefront.
// Chunks > 0 start uniform WARM steps early; the final warmup renorm lands on
// t = c*CL-1 (global cadence-aligned) so logged sums match the exact chain.
__global__ void __launch_bounds__(512, 2)
hmm_fwd(const float* __restrict__ inputs,
        const float* __restrict__ Al,
        const float* __restrict__ Bl,
        const float* __restrict__ Il,
        float* __restrict__ out) {
    const int tid  = threadIdx.x;
    const int c    = blockIdx.x & 3;
    const int b    = blockIdx.x >> 2;
    const int j    = tid >> 2;
    const int h    = tid & 3;
    const int lane = tid & 31;
    const int warp = tid >> 5;

    const int tokBase  = c * CL - (c ? WARM : 0);
    const int tStart   = tokBase + 1;
    const int tEnd     = (c + 1) * CL;             // exclusive
    const int logStart = c * CL;
    const int tokCnt   = tEnd - tokBase;

    __shared__ float sB[NA * NS];                       // 16 KB emissions
    __shared__ __align__(16) unsigned char sTok[TOKMAX];
    __shared__ __align__(16) float sAl[2][144];         // quarter-padded alpha
    __shared__ float sPart[16];
    __shared__ float sMaxA[NS], sInvA[NS], sI[NS];

    // ---- prep, spread over 512 threads ----
    if (tid < NS) {                       // A row softmax stats (axis 1)
        const float* rp = Al + tid * NS;
        float m = -1e30f;
        for (int k = 0; k < NS; k += 4) {
            float4 v = *(const float4*)(rp + k);
            m = fmaxf(m, fmaxf(fmaxf(v.x, v.y), fmaxf(v.z, v.w)));
        }
        float s = 0.f;
        for (int k = 0; k < NS; k += 4) {
            float4 v = *(const float4*)(rp + k);
            s += __expf(v.x - m) + __expf(v.y - m) + __expf(v.z - m) + __expf(v.w - m);
        }
        sMaxA[tid] = m;
        sInvA[tid] = 1.f / s;
    } else if (tid < 2 * NS) {            // I softmax
        int r = tid - NS;
        float m = -1e30f;
        for (int k = 0; k < NS; k++) m = fmaxf(m, Il[k]);
        float s = 0.f;
        for (int k = 0; k < NS; k++) s += __expf(Il[k] - m);
        sI[r] = __expf(Il[r] - m) / s;
    } else if (tid < 3 * NS) {            // B softmax over alphabet per state
        int r = tid - 2 * NS;
        float m = -1e30f;
        for (int a = 0; a < NA; a++) m = fmaxf(m, Bl[a * NS + r]);
        float s = 0.f;
        for (int a = 0; a < NA; a++) s += __expf(Bl[a * NS + r] - m);
        float inv = 1.f / s;
        for (int a = 0; a < NA; a++)
            sB[a * NS + r] = __expf(Bl[a * NS + r] - m) * inv;
    }
    // one-hot -> token for this chunk's range
    {
        const float* base = inputs + ((size_t)b * NT + tokBase) * NA;
        for (int n = tid; n < tokCnt; n += 512) {
            const float4* p = (const float4*)(base + (size_t)n * NA);
            float tk = 0.f;
#pragma unroll
            for (int k = 0; k < 8; k++) {
                float4 v = p[k];
                tk += v.x * (float)(4 * k) + v.y * (float)(4 * k + 1) +
                      v.z * (float)(4 * k + 2) + v.w * (float)(4 * k + 3);
            }
            sTok[n] = (unsigned char)(int)(tk + 0.5f);
        }
    }
    __syncthreads();

    // ---- A-column registers: rows [32h, 32h+32) of column j, 16 packed f32x2 ----
    ull aR[16];
#pragma unroll
    for (int k = 0; k < 16; k++) {
        int i0 = (h << 5) + 2 * k;
        float a0 = __expf(Al[i0 * NS + j] - sMaxA[i0]) * sInvA[i0];
        float a1 = __expf(Al[(i0 + 1) * NS + j] - sMaxA[i0 + 1]) * sInvA[i0 + 1];
        aR[k] = pack2(a0, a1);
    }
    const int wOff = j + ((j >> 5) << 2);  // 36*(j>>5) + (j&31)

    // ---- init alpha at t = tokBase ----
    if (h == 0) {
        sAl[0][wOff] = (c == 0) ? sI[j] * sB[sTok[0] * NS + j] : 1.0f;
    }
    __syncthreads();

    float loglik = 0.0f;

    auto step = [&](int t, const float* rd, float* wr) {
        int tok = sTok[t - tokBase];
        float e = sB[tok * NS + j];
        const ulonglong2* al = (const ulonglong2*)((const char*)rd + h * 144);
        ull acc0 = 0ull, acc1 = 0ull;
#pragma unroll
        for (int k = 0; k < 8; k++) {
            ulonglong2 q = al[k];
            ffma2(acc0, q.x, aR[2 * k]);
            ffma2(acc1, q.y, aR[2 * k + 1]);
        }
        acc0 = add2(acc0, acc1);
        float lo, hi;
        unpack2(lo, hi, acc0);
        float p = lo + hi;
        p += __shfl_xor_sync(0xffffffffu, p, 1);   // combine quarters
        p += __shfl_xor_sync(0xffffffffu, p, 2);
        float v = p * e;

        if ((t & 7) == 7) {  // renormalize every 8 steps (aligned cadence)
            // v is quad-duplicated; xor over lane bits 2..4 sums the warp's
            // 8 distinct states without double-counting -> S is exact.
            float w = v;
            w += __shfl_xor_sync(0xffffffffu, w, 4);
            w += __shfl_xor_sync(0xffffffffu, w, 8);
            w += __shfl_xor_sync(0xffffffffu, w, 16);
            if (lane == 0) sPart[warp] = w;
            __syncthreads();
            float4 q0 = ((const float4*)sPart)[0];
            float4 q1 = ((const float4*)sPart)[1];
            float4 q2 = ((const float4*)sPart)[2];
            float4 q3 = ((const float4*)sPart)[3];
            float S = (((q0.x + q0.y) + (q0.z + q0.w)) +
                       ((q1.x + q1.y) + (q1.z + q1.w))) +
                      (((q2.x + q2.y) + (q2.z + q2.w)) +
                       ((q3.x + q3.y) + (q3.z + q3.w)));
            v *= __fdividef(1.0f, S);
            if (t >= logStart) loglik += __logf(S);
        }

        if (h == 0) wr[wOff] = v;
        __syncthreads();
    };

    float* A0 = sAl[0];
    float* A1 = sAl[1];

    // step counts are odd for every chunk (1023 or 1055)
    step(tStart, A0, A1);
    for (int t = tStart + 1; t < tEnd; t += 2) {
        step(t, A1, A0);
        step(t + 1, A0, A1);
    }

    if (tid == 0) atomicAdd(&out[b], loglik);
}

// ---------------- launch ----------------
extern "C" void kernel_launch(void* const* d_in, const int* in_sizes, int n_in,
                              void* d_out, int out_size) {
    const float* inputs = nullptr;   // 64*4096*32 = 8388608
    const float* A_logits = nullptr; // 128*128    = 16384
    const float* B_logits = nullptr; // 32*128     = 4096
    const float* I_logits = nullptr; // 128
    for (int i = 0; i < n_in; i++) {
        switch (in_sizes[i]) {
            case NB * NT * NA: inputs = (const float*)d_in[i]; break;
            case NS * NS:      A_logits = (const float*)d_in[i]; break;
            case NA * NS:      B_logits = (const float*)d_in[i]; break;
            case NS:           I_logits = (const float*)d_in[i]; break;
        }
    }
    float* out = (float*)d_out;
    zero_out<<<1, NB>>>(out);
    hmm_fwd<<<NB * NC, 512>>>(inputs, A_logits, B_logits, I_logits, out);
}

// round 10
// speedup vs baseline: 9.2896x; 9.2896x over previous
#include <cuda_runtime.h>
#include <cuda_bf16.h>
#include <cstdint>

#define NS 128
#define NA 32
#define NB 64
#define NT 4096

#define NC    32           // chunks per batch
#define SPAN  128          // logged steps per chunk (multiple of 8)
#define WARM  32           // warmup steps (multiple of 8)

// alpha SMEM layout (bf16x2 words): word addr = 80*row + 20*q + idx
// (row 0..15, phase q = pair_index&3, idx = pair_index>>2 in 0..15).
// Strides chosen so each LDS.128 8-lane subgroup covers 8 distinct bank-groups.

__global__ void zero_out(float* out) { out[threadIdx.x] = 0.0f; }

__device__ __forceinline__ unsigned pack_bf(float lo, float hi) {
    unsigned d;
    asm("cvt.rn.bf16x2.f32 %0, %1, %2;" : "=r"(d) : "f"(hi), "f"(lo));
    return d;
}

__device__ __forceinline__ void mma16816(
    float& c0, float& c1, float& c2, float& c3,
    unsigned a0, unsigned a1, unsigned a2, unsigned a3,
    unsigned b0, unsigned b1)
{
    asm volatile(
        "mma.sync.aligned.m16n8k16.row.col.f32.bf16.bf16.f32 "
        "{%0,%1,%2,%3}, {%4,%5,%6,%7}, {%8,%9}, {%0,%1,%2,%3};"
        : "+f"(c0), "+f"(c1), "+f"(c2), "+f"(c3)
        : "r"(a0), "r"(a1), "r"(a2), "r"(a3), "r"(b0), "r"(b1));
}

// grid = NC*4 = 128 CTAs, 256 threads (8 warps).
// CTA: chunk c = blockIdx>>2, batch group bg = blockIdx&3 -> 16 streams
// (batches bg*16 .. bg*16+15, all at the same chunk c -> lockstep MMA rows).
// Warp w owns n-states [16w, 16w+16) = 2 mma n-tiles; A-matrix fragments for
// those states are precomputed into registers (Bf: 32 regs).
// chunk 0: exact init at t=0. chunk c>0: uniform init WARM steps early; the
// final warmup renorm lands on t = c*SPAN-1 (global cadence-aligned) so the
// logged renorm sums match the exact chain (validated R7/R8).
__global__ void __launch_bounds__(256)
hmm_fwd(const float* __restrict__ inputs,
        const float* __restrict__ Al,
        const float* __restrict__ Bl,
        const float* __restrict__ Il,
        float* __restrict__ out) {
    const int tid  = threadIdx.x;
    const int w    = tid >> 5;
    const int lane = tid & 31;
    const int g    = lane >> 2;   // 0..7  (mma group)
    const int q    = lane & 3;    // 0..3  (thread-in-group)
    const int c    = blockIdx.x >> 2;
    const int bg   = blockIdx.x & 3;

    const int tokBase  = c * SPAN - (c ? WARM : 0);
    const int tStart   = tokBase + 1;
    const int tEnd     = (c + 1) * SPAN;     // exclusive
    const int logStart = c * SPAN;
    const int tokCnt   = tEnd - tokBase;     // 128 or 160

    __shared__ float sB[NA * 132];                  // emissions, padded rows
    __shared__ unsigned char sTok[16][160];
    __shared__ __align__(16) unsigned sAF[2][1280]; // alpha bf16x2, permuted
    __shared__ float sPart[8][16];
    __shared__ float sS[16];
    __shared__ float sMaxA[NS], sInvA[NS], sI[NS];

    // ---- prep: softmax stats (threads 0..127), tokens (all) ----
    if (tid < NS) {
        {   // A row softmax stats (axis 1)
            const float* rp = Al + tid * NS;
            float m = -1e30f;
            for (int k = 0; k < NS; k += 4) {
                float4 v = *(const float4*)(rp + k);
                m = fmaxf(m, fmaxf(fmaxf(v.x, v.y), fmaxf(v.z, v.w)));
            }
            float s = 0.f;
            for (int k = 0; k < NS; k += 4) {
                float4 v = *(const float4*)(rp + k);
                s += __expf(v.x - m) + __expf(v.y - m) + __expf(v.z - m) + __expf(v.w - m);
            }
            sMaxA[tid] = m;
            sInvA[tid] = 1.f / s;
        }
        {   // I softmax
            float m = -1e30f;
            for (int k = 0; k < NS; k++) m = fmaxf(m, Il[k]);
            float s = 0.f;
            for (int k = 0; k < NS; k++) s += __expf(Il[k] - m);
            sI[tid] = __expf(Il[tid] - m) / s;
        }
        {   // B softmax over alphabet, state column tid
            float m = -1e30f;
            for (int a = 0; a < NA; a++) m = fmaxf(m, Bl[a * NS + tid]);
            float s = 0.f;
            for (int a = 0; a < NA; a++) s += __expf(Bl[a * NS + tid] - m);
            float inv = 1.f / s;
            for (int a = 0; a < NA; a++)
                sB[a * 132 + tid] = __expf(Bl[a * NS + tid] - m) * inv;
        }
    }
    // tokens: 16 streams x tokCnt
    for (int r = 0; r < 16; r++) {
        const float* base = inputs + ((size_t)(bg * 16 + r) * NT + tokBase) * NA;
        for (int n = tid; n < tokCnt; n += 256) {
            const float4* p = (const float4*)(base + (size_t)n * NA);
            float tk = 0.f;
#pragma unroll
            for (int k = 0; k < 8; k++) {
                float4 v = p[k];
                tk += v.x * (float)(4 * k) + v.y * (float)(4 * k + 1) +
                      v.z * (float)(4 * k + 2) + v.w * (float)(4 * k + 3);
            }
            sTok[r][n] = (unsigned char)(int)(tk + 0.5f);
        }
    }
    __syncthreads();

    // ---- B-fragments: transition matrix for this warp's 2 n-tiles ----
    // b0: k = {2q+16kt, 2q+16kt+1}, b1: k+8; n = tile*8 + g.
    unsigned Bf[2][8][2];
#pragma unroll
    for (int i = 0; i < 2; i++) {
        int n = (2 * w + i) * 8 + g;
#pragma unroll
        for (int kt = 0; kt < 8; kt++) {
            int k0 = 16 * kt + 2 * q;
            float a00 = __expf(Al[k0 * NS + n] - sMaxA[k0]) * sInvA[k0];
            float a01 = __expf(Al[(k0 + 1) * NS + n] - sMaxA[k0 + 1]) * sInvA[k0 + 1];
            Bf[i][kt][0] = pack_bf(a00, a01);
            int k1 = k0 + 8;
            float a10 = __expf(Al[k1 * NS + n] - sMaxA[k1]) * sInvA[k1];
            float a11 = __expf(Al[(k1 + 1) * NS + n] - sMaxA[k1 + 1]) * sInvA[k1 + 1];
            Bf[i][kt][1] = pack_bf(a10, a11);
        }
    }

    // ---- init alpha at t = tokBase into buffer 0 ----
    for (int idx = tid; idx < 16 * 64; idx += 256) {
        int row = idx >> 6, pi = idx & 63;
        int n = 2 * pi;
        float v0, v1;
        if (c == 0) {
            int tk = sTok[row][0];
            v0 = sI[n] * sB[tk * 132 + n];
            v1 = sI[n + 1] * sB[tk * 132 + n + 1];
        } else {
            v0 = v1 = 1.0f;   // uniform direction, contraction fixes it
        }
        sAF[0][80 * row + 20 * (pi & 3) + (pi >> 2)] = pack_bf(v0, v1);
    }
    __syncthreads();

    float ll = 0.0f;   // stream loglik, owned by threads tid<16

    auto step = [&](int t, const unsigned* rd, unsigned* wr) {
        int tt = t - tokBase;
        int tok0 = sTok[g][tt];
        int tok1 = sTok[g + 8][tt];

        // stage this thread's alpha slices (rows g, g+8; phase q)
        unsigned w0[16], w1[16];
        {
            const uint4* p0 = (const uint4*)(rd + 80 * g + 20 * q);
            const uint4* p1 = (const uint4*)(rd + 80 * (g + 8) + 20 * q);
#pragma unroll
            for (int m = 0; m < 4; m++) {
                uint4 u = p0[m];
                w0[4 * m] = u.x; w0[4 * m + 1] = u.y; w0[4 * m + 2] = u.z; w0[4 * m + 3] = u.w;
                uint4 v = p1[m];
                w1[4 * m] = v.x; w1[4 * m + 1] = v.y; w1[4 * m + 2] = v.z; w1[4 * m + 3] = v.w;
            }
        }

        float acc[2][4] = {{0.f, 0.f, 0.f, 0.f}, {0.f, 0.f, 0.f, 0.f}};
#pragma unroll
        for (int kt = 0; kt < 8; kt++) {
            unsigned a0 = w0[2 * kt], a2 = w0[2 * kt + 1];
            unsigned a1 = w1[2 * kt], a3 = w1[2 * kt + 1];
            mma16816(acc[0][0], acc[0][1], acc[0][2], acc[0][3],
                     a0, a1, a2, a3, Bf[0][kt][0], Bf[0][kt][1]);
            mma16816(acc[1][0], acc[1][1], acc[1][2], acc[1][3],
                     a0, a1, a2, a3, Bf[1][kt][0], Bf[1][kt][1]);
        }

        // emission multiply (per-element: row-dependent token, col-dependent state)
        float v[2][4];
#pragma unroll
        for (int i = 0; i < 2; i++) {
            int n = (2 * w + i) * 8 + 2 * q;
            float2 e0 = *(const float2*)(sB + tok0 * 132 + n);
            float2 e1 = *(const float2*)(sB + tok1 * 132 + n);
            v[i][0] = acc[i][0] * e0.x;
            v[i][1] = acc[i][1] * e0.y;
            v[i][2] = acc[i][2] * e1.x;
            v[i][3] = acc[i][3] * e1.y;
        }

        if ((t & 7) == 7) {  // renormalize every 8 steps (aligned cadence)
            float s0 = (v[0][0] + v[0][1]) + (v[1][0] + v[1][1]);   // row g
            float s1 = (v[0][2] + v[0][3]) + (v[1][2] + v[1][3]);   // row g+8
            s0 += __shfl_xor_sync(0xffffffffu, s0, 1);
            s0 += __shfl_xor_sync(0xffffffffu, s0, 2);
            s1 += __shfl_xor_sync(0xffffffffu, s1, 1);
            s1 += __shfl_xor_sync(0xffffffffu, s1, 2);
            if (q == 0) { sPart[w][g] = s0; sPart[w][g + 8] = s1; }
            __syncthreads();
            if (tid < 16) {
                float S = 0.f;
#pragma unroll
                for (int ww = 0; ww < 8; ww++) S += sPart[ww][tid];
                sS[tid] = S;
                if (t >= logStart) ll += __logf(S);
            }
            __syncthreads();
            float i0 = __fdividef(1.0f, sS[g]);
            float i1 = __fdividef(1.0f, sS[g + 8]);
#pragma unroll
            for (int i = 0; i < 2; i++) {
                v[i][0] *= i0; v[i][1] *= i0;
                v[i][2] *= i1; v[i][3] *= i1;
            }
        }

        // pack + write both rows (tile pair -> consecutive idx 2w, 2w+1)
        uint2 o0, o1;
        o0.x = pack_bf(v[0][0], v[0][1]); o0.y = pack_bf(v[1][0], v[1][1]);
        o1.x = pack_bf(v[0][2], v[0][3]); o1.y = pack_bf(v[1][2], v[1][3]);
        *(uint2*)(wr + 80 * g + 20 * q + 2 * w) = o0;
        *(uint2*)(wr + 80 * (g + 8) + 20 * q + 2 * w) = o1;
        __syncthreads();
    };

    unsigned* B0 = sAF[0];
    unsigned* B1 = sAF[1];

    // step counts: 127 (c==0) or 159 (c>0) -> odd for both
    step(tStart, B0, B1);
    for (int t = tStart + 1; t < tEnd; t += 2) {
        step(t, B1, B0);
        step(t + 1, B0, B1);
    }

    if (tid < 16) atomicAdd(&out[bg * 16 + tid], ll);
}

// ---------------- launch ----------------
extern "C" void kernel_launch(void* const* d_in, const int* in_sizes, int n_in,
                              void* d_out, int out_size) {
    const float* inputs = nullptr;   // 64*4096*32 = 8388608
    const float* A_logits = nullptr; // 128*128    = 16384
    const float* B_logits = nullptr; // 32*128     = 4096
    const float* I_logits = nullptr; // 128
    for (int i = 0; i < n_in; i++) {
        switch (in_sizes[i]) {
            case NB * NT * NA: inputs = (const float*)d_in[i]; break;
            case NS * NS:      A_logits = (const float*)d_in[i]; break;
            case NA * NS:      B_logits = (const float*)d_in[i]; break;
            case NS:           I_logits = (const float*)d_in[i]; break;
        }
    }
    float* out = (float*)d_out;
    zero_out<<<1, NB>>>(out);
    hmm_fwd<<<NC * 4, 256>>>(inputs, A_logits, B_logits, I_logits, out);
}